// round 16
// baseline (speedup 1.0000x reference)
#include <cuda_runtime.h>
#include <cuda_fp16.h>
#include <math.h>
#include <stdint.h>

// ---------------- problem constants ----------------
#define NB   128
#define LT   256
#define FH   768
#define GG   3072
#define BG   (NB*LT)

// ---- big hoisted GEMM (1-term fp16, K=768) ----
#define KH   FH              // 768
#define BK   32
#define NKH  (KH/BK)         // 24
#define ROWB 80
#define ATILE (128*ROWB)
#define STAGEB (2*ATILE)     // 20480
#define GNST 8

// ---- persistent recurrent role (1-term fp16 h, 64x64 tiles, full-resident A) ----
#define RBK   64
#define RNCH  12             // 12 A chunks (K=768)
#define NWCH  12             // 12 W chunks
#define RROW  144
#define ACHB  (64*RROW)      // 9216 per A chunk
#define WBASE (RNCH*ACHB)    // 110592
#define WCHB  (64*RROW)      // 9216 per W chunk
#define PSMEM (WBASE + NWCH*WCHB)   // 221184
#define NRB   96
#define NGB   52
#define NTILE (24*LT)
#define MEGA_SMEM PSMEM      // >= GNST*STAGEB (163840)

// ---------------- scratch (device globals) ----------------
__device__ __half g_Xp [(size_t)BG * KH];     // GAT out, fp16
__device__ __half g_Wp [(size_t)GG * KH];     // W_ih fp16
__device__ __half g_Whp[(size_t)GG * FH];     // permuted W_hh fp16 (gate-interleaved)
__device__ __half g_hp [2][(size_t)NB * FH];  // ping-pong h, fp16
__device__ float  g_XW [(size_t)BG * GG];
__device__ unsigned g_ctr2[2][32];            // per-m-half barrier counters (padded)
__device__ int      g_flag[LT];

__constant__ int c_par[24] = {-1,0,0,0,1,2,3,4,5,6,7,8,9,9,9,12,13,14,16,17,18,19,20,21};

// fast MUFU-based activations (sign-safe)
__device__ __forceinline__ float fsigm(float x) {
    float e = __expf(-x);
    return __fdividef(1.f, 1.f + e);
}
__device__ __forceinline__ float ftanh(float x) {
    float a = fabsf(x);
    float e = __expf(-2.f * a);
    float r = __fdividef(1.f - e, 1.f + e);
    return copysignf(r, x);
}

__device__ __forceinline__ uint32_t smem_u32(const void* p) {
    uint32_t a;
    asm("{ .reg .u64 t; cvta.to.shared.u64 t, %1; cvt.u32.u64 %0, t; }" : "=r"(a) : "l"(p));
    return a;
}

__device__ __forceinline__ void cp16(uint32_t s, const void* g) {
    asm volatile("cp.async.cg.shared.global [%0], [%1], 16;" :: "r"(s), "l"(g));
}

__device__ __forceinline__ void ldm_x4(uint32_t &r0, uint32_t &r1, uint32_t &r2,
                                       uint32_t &r3, uint32_t addr) {
    asm volatile("ldmatrix.sync.aligned.m8n8.x4.shared.b16 {%0,%1,%2,%3}, [%4];"
                 : "=r"(r0), "=r"(r1), "=r"(r2), "=r"(r3) : "r"(addr));
}

__device__ __forceinline__ void mma_f16(float* d, const uint32_t* a,
                                        const uint32_t* b) {
    asm volatile(
        "mma.sync.aligned.m16n8k16.row.col.f32.f16.f16.f32 "
        "{%0,%1,%2,%3}, {%4,%5,%6,%7}, {%8,%9}, {%0,%1,%2,%3};"
        : "+f"(d[0]), "+f"(d[1]), "+f"(d[2]), "+f"(d[3])
        : "r"(a[0]), "r"(a[1]), "r"(a[2]), "r"(a[3]), "r"(b[0]), "r"(b[1]));
}

// ---------------- small prep kernels ----------------
__global__ void reset_flags() {
    int i = threadIdx.x;
    if (i < 64) ((unsigned*)g_ctr2)[i] = 0u;
    if (i < LT) g_flag[i] = 0;
}

__global__ void pack_w(const float* __restrict__ W, __half* __restrict__ Wp) {
    int i = blockIdx.x * 256 + threadIdx.x;
    if (i >= GG * FH) return;
    Wp[i] = __float2half(W[i]);
}

// Gate-interleaved W_hh permutation:
// smem/global row = nb*64 + wn*16 + gh*8 + fp*2 + gl
//   gate = gh*2 + gl  (torch order i,f,g,o = 0..3)
//   feature (local)  = wn*4 + fp
// so each mma thread's 4 output columns = the 4 gates of ONE feature.
__global__ void pack_whh(const float* __restrict__ W) {
    size_t idx = (size_t)blockIdx.x * 256 + threadIdx.x;
    if (idx >= (size_t)GG * FH) return;
    int k   = (int)(idx % FH);
    int row = (int)(idx / FH);       // nb*64 + r
    int nb = row >> 6, r = row & 63;
    int wn = r >> 4, nl = r & 15;
    int gh = nl >> 3, rem = nl & 7;
    int fp = rem >> 1, gl = rem & 1;
    int gate = gh * 2 + gl;
    int fi = wn * 4 + fp;
    g_Whp[idx] = __float2half(W[(size_t)(gate * FH + nb * 16 + fi) * FH + k]);
}

// ---------------- GAT: one warp per graph (k-outer matmul) ----------------
__global__ __launch_bounds__(256) void gat_kernel(
    const float* __restrict__ src,
    const float* __restrict__ W_pre, const float* __restrict__ b_pre,
    const float* __restrict__ W_gat,
    const float* __restrict__ att_src, const float* __restrict__ att_dst,
    const float* __restrict__ b_gat,
    __half* __restrict__ Xp)
{
    __shared__ float Wg[32 * 32];
    __shared__ float xbuf[8][24][32];
    __shared__ float asd[8][24][2];

    int tid = threadIdx.x;
    for (int i = tid; i < 1024; i += 256) Wg[i] = W_gat[i];
    __syncthreads();

    int w = tid >> 5, h = tid & 31;
    int b = blockIdx.x * 8 + w;
    int n = b >> 8, l = b & 255;

    const float* s = src + (size_t)b * 72;
    float w0 = W_pre[h], w1 = W_pre[32 + h], w2 = W_pre[64 + h], bp = b_pre[h];

    #pragma unroll
    for (int j = 0; j < 24; j++) {
        float v = fmaf(s[j*3+2], w2, fmaf(s[j*3+1], w1, fmaf(s[j*3+0], w0, bp)));
        xbuf[w][j][h] = tanhf(v);
    }
    __syncwarp();

    float accj[24];
    #pragma unroll
    for (int j = 0; j < 24; j++) accj[j] = 0.f;
    #pragma unroll
    for (int k = 0; k < 32; k++) {
        float wv = Wg[k * 32 + h];
        #pragma unroll
        for (int j = 0; j < 24; j++)
            accj[j] = fmaf(xbuf[w][j][k], wv, accj[j]);
    }
    __syncwarp();

    float asrc = att_src[h], adst = att_dst[h];
    #pragma unroll
    for (int j = 0; j < 24; j++) {
        float ps = accj[j] * asrc, pd = accj[j] * adst;
        #pragma unroll
        for (int o = 16; o > 0; o >>= 1) {
            ps += __shfl_xor_sync(0xffffffffu, ps, o);
            pd += __shfl_xor_sync(0xffffffffu, pd, o);
        }
        if (h == 0) { asd[w][j][0] = ps; asd[w][j][1] = pd; }
        xbuf[w][j][h] = accj[j];
    }
    __syncwarp();

    float bg = b_gat[h];
    size_t rbase = (size_t)(l * 128 + n) * KH;
    #pragma unroll
    for (int j = 0; j < 24; j++) {
        int p = c_par[j];
        float g;
        if (p < 0) {
            g = xbuf[w][j][h];
        } else {
            float ad = asd[w][j][1];
            float es = ad + asd[w][j][0];
            float ep = ad + asd[w][p][0];
            es = es > 0.f ? es : 0.2f * es;
            ep = ep > 0.f ? ep : 0.2f * ep;
            float m  = fmaxf(es, ep);
            float ws = __expf(es - m), wp = __expf(ep - m);
            float inv = __fdividef(1.f, ws + wp);
            g = (ws * xbuf[w][j][h] + wp * xbuf[w][p][h]) * inv;
        }
        Xp[rbase + j * 32 + h] = __float2half(g + bg);
    }
}

// ---------------- mega kernel ----------------
__global__ __launch_bounds__(256, 1) void mega(
    const float* __restrict__ bih, const float* __restrict__ bhh,
    float* __restrict__ out)
{
    extern __shared__ __align__(16) char sm[];
    const uint32_t smb = smem_u32(sm);

    const int tid  = threadIdx.x;
    const int lane = tid & 31;
    const int warp = tid >> 5;

    if (blockIdx.x >= NRB) {
        // ================= producer role: 1-term fp16 GEMM =================
        const int gb = blockIdx.x - NRB;
        const __half* Ap = g_Xp;
        const __half* Bp = g_Wp;
        float* C = g_XW;

        const int wm = warp >> 2;
        const int wn = warp & 3;
        const int ldRow = tid >> 2;
        const int ldSeg = tid & 3;
        const uint32_t stRow = ldRow * ROWB + ldSeg * 16;
        const uint32_t aOff = (uint32_t)((wm * 64 + (lane & 7) + ((lane >> 3) & 1) * 8) * ROWB
                                         + ((lane >> 4) & 1) * 16);
        const uint32_t bOff = (uint32_t)(ATILE + (wn * 32 + (lane & 7) + ((lane >> 4) & 1) * 8) * ROWB
                                         + ((lane >> 3) & 1) * 16);

        for (int tile = gb; tile < NTILE; tile += NGB) {
            const int y = tile / 24;
            const int x = tile % 24;
            const int m0 = y * 128;
            const int n0 = x * 128;

            const __half* gA = Ap + (size_t)(m0 + ldRow) * KH + ldSeg * 8;
            const __half* gB = Bp + (size_t)(n0 + ldRow) * KH + ldSeg * 8;

            float acc[4][4][4];
            #pragma unroll
            for (int i = 0; i < 4; i++)
                #pragma unroll
                for (int j = 0; j < 4; j++)
                    #pragma unroll
                    for (int q = 0; q < 4; q++) acc[i][j][q] = 0.f;

            #pragma unroll
            for (int pc = 0; pc < GNST - 1; pc++) {
                uint32_t sb = smb + pc * STAGEB;
                int ko = pc * BK;
                #pragma unroll
                for (int i = 0; i < 2; i++) {
                    cp16(sb + stRow + i * 64 * ROWB,         gA + (size_t)i * 64 * KH + ko);
                    cp16(sb + ATILE + stRow + i * 64 * ROWB, gB + (size_t)i * 64 * KH + ko);
                }
                asm volatile("cp.async.commit_group;");
            }

            for (int kc = 0; kc < NKH; kc++) {
                asm volatile("cp.async.wait_group %0;" :: "n"(GNST - 2));
                __syncthreads();

                if (kc + GNST - 1 < NKH) {
                    uint32_t sb = smb + ((kc + GNST - 1) & (GNST - 1)) * STAGEB;
                    int ko = (kc + GNST - 1) * BK;
                    #pragma unroll
                    for (int i = 0; i < 2; i++) {
                        cp16(sb + stRow + i * 64 * ROWB,         gA + (size_t)i * 64 * KH + ko);
                        cp16(sb + ATILE + stRow + i * 64 * ROWB, gB + (size_t)i * 64 * KH + ko);
                    }
                }
                asm volatile("cp.async.commit_group;");

                const uint32_t soff = smb + (kc & (GNST - 1)) * STAGEB;
                #pragma unroll
                for (int ks = 0; ks < 2; ks++) {
                    uint32_t a[4][4], bq[4][2];
                    #pragma unroll
                    for (int tm = 0; tm < 4; tm++)
                        ldm_x4(a[tm][0], a[tm][1], a[tm][2], a[tm][3],
                               soff + aOff + tm * (16 * ROWB) + ks * 32);
                    #pragma unroll
                    for (int tb = 0; tb < 2; tb++) {
                        uint32_t r0, r1, r2, r3;
                        ldm_x4(r0, r1, r2, r3, soff + bOff + tb * (16 * ROWB) + ks * 32);
                        bq[2*tb][0] = r0; bq[2*tb][1] = r1;
                        bq[2*tb+1][0] = r2; bq[2*tb+1][1] = r3;
                    }
                    #pragma unroll
                    for (int tm = 0; tm < 4; tm++)
                        #pragma unroll
                        for (int tn = 0; tn < 4; tn++)
                            mma_f16(acc[tm][tn], a[tm], bq[tn]);
                }
            }
            asm volatile("cp.async.wait_group 0;");

            #pragma unroll
            for (int tm = 0; tm < 4; tm++) {
                int row = m0 + wm * 64 + tm * 16 + (lane >> 2);
                #pragma unroll
                for (int tn = 0; tn < 4; tn++) {
                    int col = n0 + wn * 32 + tn * 8 + (lane & 3) * 2;
                    float* p = C + (size_t)row * GG + col;
                    *(float2*)p                    = make_float2(acc[tm][tn][0], acc[tm][tn][1]);
                    *(float2*)(p + (size_t)8 * GG) = make_float2(acc[tm][tn][2], acc[tm][tn][3]);
                }
            }

            __threadfence();
            __syncthreads();
            if (tid == 0) atomicAdd(&g_flag[y], 1);
            __syncthreads();
        }
        return;
    }

    // ====== consumer role: persistent LSTM (register-resident gate epilogue) ======
    const int b  = blockIdx.x;
    const int mb = b & 1;
    const int nb = b >> 1;
    const int m0 = mb * 64;

    const int wm = warp >> 2;        // 0..1: 32-row m strip
    const int wn = warp & 3;         // 0..3: 16-row n strip (4 features x 4 gates)

    const int fp   = lane & 3;
    const int feat = nb * 16 + wn * 4 + fp;
    const int mbase = m0 + wm * 32 + (lane >> 2);   // + tm*16 + rr*8

    // one-time resident W slice (12 chunks x 64 rows x 64 halfs)
    {
        const __half* Wb = g_Whp + (size_t)nb * 64 * FH;
        for (int i = tid; i < NWCH * 512; i += 256) {
            int chunk = i >> 9;
            int rem   = i & 511;
            int row   = rem >> 3, seg = rem & 7;
            cp16(smb + WBASE + chunk * WCHB + row * RROW + seg * 16,
                 Wb + (size_t)row * FH + chunk * RBK + seg * 8);
        }
        asm volatile("cp.async.commit_group;");
        asm volatile("cp.async.wait_group 0;");
    }

    float bias_r[4];
    #pragma unroll
    for (int g = 0; g < 4; g++) bias_r[g] = bih[g * FH + feat] + bhh[g * FH + feat];

    float creg[4] = {0.f, 0.f, 0.f, 0.f};   // cells: idx = tm*2 + rr

    __syncthreads();

    const uint32_t aOff = (uint32_t)((wm * 32 + (lane & 15)) * RROW
                                     + ((lane >> 4) & 1) * 16);
    const uint32_t bOffW = (uint32_t)((wn * 16 + (lane & 7) + ((lane >> 4) & 1) * 8) * RROW
                                      + ((lane >> 3) & 1) * 16);

    unsigned* ctr = &g_ctr2[mb][0];
    const float* xwbase = g_XW;

    for (int t = 0; t < LT; t++) {
        const __half* hin   = g_hp[(t + 1) & 1];
        __half*       houtp = g_hp[t & 1];
        const float*  xw    = xwbase + (size_t)t * NB * GG;

        // ---- combined waits: xw[t] tiles ready + same-half h[t-1] published ----
        if (tid == 0) {
            while (*(volatile int*)&g_flag[t] < 24) { __nanosleep(64); }
            if (t > 0) {
                unsigned target = 48u * (unsigned)t;
                while (*(volatile unsigned*)ctr < target) { __nanosleep(32); }
            }
            __threadfence();
        }
        __syncthreads();

        // ---- issue h loads FIRST so xw LDG overlaps them ----
        if (t > 0) {
            #pragma unroll
            for (int j = 0; j < 12; j++) {
                int i = tid + j * 256;
                int chunk = i >> 9;
                int rem   = i & 511;
                int row   = rem >> 3, seg = rem & 7;
                cp16(smb + chunk * ACHB + row * RROW + seg * 16,
                     hin + (size_t)(m0 + row) * FH + chunk * RBK + seg * 8);
            }
            asm volatile("cp.async.commit_group;");
            #pragma unroll
            for (int j = 12; j < 24; j++) {
                int i = tid + j * 256;
                int chunk = i >> 9;
                int rem   = i & 511;
                int row   = rem >> 3, seg = rem & 7;
                cp16(smb + chunk * ACHB + row * RROW + seg * 16,
                     hin + (size_t)(m0 + row) * FH + chunk * RBK + seg * 8);
            }
            asm volatile("cp.async.commit_group;");
        }

        // xw prefetch for this thread's 4 cells (overlaps cp.async)
        float xwv[4][4];
        #pragma unroll
        for (int tm = 0; tm < 2; tm++)
            #pragma unroll
            for (int rr = 0; rr < 2; rr++) {
                int m = mbase + tm * 16 + rr * 8;
                const float* xwr = xw + (size_t)m * GG + feat;
                int idx = tm * 2 + rr;
                xwv[idx][0] = xwr[0];
                xwv[idx][1] = xwr[FH];
                xwv[idx][2] = xwr[2 * FH];
                xwv[idx][3] = xwr[3 * FH];
            }

        float acc[2][2][4];
        #pragma unroll
        for (int i = 0; i < 2; i++)
            #pragma unroll
            for (int j = 0; j < 2; j++)
                #pragma unroll
                for (int q = 0; q < 4; q++) acc[i][j][q] = 0.f;

        if (t > 0) {
            asm volatile("cp.async.wait_group 1;");
            __syncthreads();
            #pragma unroll
            for (int kc = 0; kc < 6; kc++) {
                const uint32_t soff = smb + kc * ACHB;
                const uint32_t woff = smb + WBASE + kc * WCHB;
                #pragma unroll
                for (int ks = 0; ks < RBK / 16; ks++) {
                    uint32_t a[2][4], bq[2][2];
                    #pragma unroll
                    for (int tm = 0; tm < 2; tm++)
                        ldm_x4(a[tm][0], a[tm][1], a[tm][2], a[tm][3],
                               soff + aOff + tm * (16 * RROW) + ks * 32);
                    {
                        uint32_t r0, r1, r2, r3;
                        ldm_x4(r0, r1, r2, r3, woff + bOffW + ks * 32);
                        bq[0][0] = r0; bq[0][1] = r1;
                        bq[1][0] = r2; bq[1][1] = r3;
                    }
                    #pragma unroll
                    for (int tm = 0; tm < 2; tm++)
                        #pragma unroll
                        for (int tn = 0; tn < 2; tn++)
                            mma_f16(acc[tm][tn], a[tm], bq[tn]);
                }
            }

            asm volatile("cp.async.wait_group 0;");
            __syncthreads();
            #pragma unroll
            for (int kc = 6; kc < 12; kc++) {
                const uint32_t soff = smb + kc * ACHB;
                const uint32_t woff = smb + WBASE + kc * WCHB;
                #pragma unroll
                for (int ks = 0; ks < RBK / 16; ks++) {
                    uint32_t a[2][4], bq[2][2];
                    #pragma unroll
                    for (int tm = 0; tm < 2; tm++)
                        ldm_x4(a[tm][0], a[tm][1], a[tm][2], a[tm][3],
                               soff + aOff + tm * (16 * RROW) + ks * 32);
                    {
                        uint32_t r0, r1, r2, r3;
                        ldm_x4(r0, r1, r2, r3, woff + bOffW + ks * 32);
                        bq[0][0] = r0; bq[0][1] = r1;
                        bq[1][0] = r2; bq[1][1] = r3;
                    }
                    #pragma unroll
                    for (int tm = 0; tm < 2; tm++)
                        #pragma unroll
                        for (int tn = 0; tn < 2; tn++)
                            mma_f16(acc[tm][tn], a[tm], bq[tn]);
                }
            }
        }

        // ---- register-resident epilogue: gates of cell (tm, rr) live in acc ----
        // gi = acc[tm][0][rr*2+0], gf = acc[tm][0][rr*2+1],
        // gg = acc[tm][1][rr*2+0], go = acc[tm][1][rr*2+1]
        float hvv[4];
        #pragma unroll
        for (int tm = 0; tm < 2; tm++)
            #pragma unroll
            for (int rr = 0; rr < 2; rr++) {
                int idx = tm * 2 + rr;
                int m = mbase + tm * 16 + rr * 8;

                float gi = acc[tm][0][rr*2+0] + xwv[idx][0] + bias_r[0];
                float gf = acc[tm][0][rr*2+1] + xwv[idx][1] + bias_r[1];
                float gg = acc[tm][1][rr*2+0] + xwv[idx][2] + bias_r[2];
                float go = acc[tm][1][rr*2+1] + xwv[idx][3] + bias_r[3];

                float c  = fsigm(gf) * creg[idx] + fsigm(gi) * ftanh(gg);
                float hv = fsigm(go) * ftanh(c);
                creg[idx] = c;
                hvv[idx] = hv;

                houtp[(size_t)m * FH + feat] = __float2half(hv);
            }

        __threadfence();
        __syncthreads();         // all h stores done + all ldmatrix reads done
        if (tid == 0) atomicAdd(ctr, 1u);

        // out stores overlap other blocks' arrivals
        #pragma unroll
        for (int tm = 0; tm < 2; tm++)
            #pragma unroll
            for (int rr = 0; rr < 2; rr++) {
                int idx = tm * 2 + rr;
                int m = mbase + tm * 16 + rr * 8;
                out[((size_t)m * LT + t) * FH + feat] = hvv[idx];
                if (t == LT - 1) {
                    out[(size_t)NB * LT * FH + (size_t)m * FH + feat]           = hvv[idx];
                    out[(size_t)NB * LT * FH + NB * FH + (size_t)m * FH + feat] = creg[idx];
                }
            }
    }
}

// ---------------- launch ----------------
extern "C" void kernel_launch(void* const* d_in, const int* in_sizes, int n_in,
                              void* d_out, int out_size)
{
    const float* src     = (const float*)d_in[0];
    const float* W_pre   = (const float*)d_in[1];
    const float* b_pre   = (const float*)d_in[2];
    const float* W_gat   = (const float*)d_in[3];
    const float* att_src = (const float*)d_in[4];
    const float* att_dst = (const float*)d_in[5];
    const float* b_gat   = (const float*)d_in[6];
    const float* W_ih    = (const float*)d_in[7];
    const float* W_hh    = (const float*)d_in[8];
    const float* b_ih    = (const float*)d_in[9];
    const float* b_hh    = (const float*)d_in[10];
    float* out = (float*)d_out;

    __half *Xp, *Wp;
    cudaGetSymbolAddress((void**)&Xp,  g_Xp);
    cudaGetSymbolAddress((void**)&Wp,  g_Wp);

    cudaFuncSetAttribute(mega, cudaFuncAttributeMaxDynamicSharedMemorySize,
                         MEGA_SMEM);

    // 0) prep
    reset_flags<<<1, 256>>>();
    pack_w<<<(GG * FH + 255) / 256, 256>>>(W_ih, Wp);
    pack_whh<<<(unsigned)(((size_t)GG * FH + 255) / 256), 256>>>(W_hh);

    // 1) GAT -> fp16 X
    gat_kernel<<<BG / 8, 256>>>(src, W_pre, b_pre, W_gat, att_src, att_dst, b_gat, Xp);

    // 2) fused producer-GEMM + persistent-LSTM
    mega<<<NRB + NGB, 256, MEGA_SMEM>>>(b_ih, b_hh, out);
}

// round 17
// speedup vs baseline: 1.0466x; 1.0466x over previous
#include <cuda_runtime.h>
#include <cuda_fp16.h>
#include <math.h>
#include <stdint.h>

// ---------------- problem constants ----------------
#define NB   128
#define LT   256
#define FH   768
#define GG   3072
#define BG   (NB*LT)

// ---- big hoisted GEMM (1-term fp16, K=768) ----
#define KH   FH              // 768
#define BK   32
#define NKH  (KH/BK)         // 24
#define ROWB 80
#define ATILE (128*ROWB)
#define STAGEB (2*ATILE)     // 20480
#define GNST 8

// ---- persistent recurrent role (1-term fp16 h, 64x64 tiles, full-resident A) ----
#define RBK   64
#define RNCH  12             // 12 A chunks (K=768)
#define NWCH  12             // 12 W chunks
#define RROW  144
#define ACHB  (64*RROW)      // 9216 per A chunk
#define WBASE (RNCH*ACHB)    // 110592
#define WCHB  (64*RROW)      // 9216 per W chunk
#define PSMEM (WBASE + NWCH*WCHB)   // 221184
#define NRB   96
#define NGB   52
#define NTILE (24*LT)
#define MEGA_SMEM PSMEM      // >= GNST*STAGEB (163840)

// ---------------- scratch (device globals) ----------------
__device__ __half g_Xp [(size_t)BG * KH];     // GAT out, fp16
__device__ __half g_Wp [(size_t)GG * KH];     // W_ih fp16
__device__ __half g_Whp[(size_t)GG * FH];     // permuted W_hh fp16 (gate-interleaved)
__device__ __half g_hp [2][(size_t)NB * FH];  // ping-pong h, fp16
__device__ float  g_XW [(size_t)BG * GG];
__device__ unsigned g_ctr2[2][32];            // per-m-half barrier counters (padded)
__device__ unsigned g_flag[LT];

__constant__ int c_par[24] = {-1,0,0,0,1,2,3,4,5,6,7,8,9,9,9,12,13,14,16,17,18,19,20,21};

// fast MUFU-based activations (sign-safe)
__device__ __forceinline__ float fsigm(float x) {
    float e = __expf(-x);
    return __fdividef(1.f, 1.f + e);
}
__device__ __forceinline__ float ftanh(float x) {
    float a = fabsf(x);
    float e = __expf(-2.f * a);
    float r = __fdividef(1.f - e, 1.f + e);
    return copysignf(r, x);
}

// release/acquire primitives (gpu scope) — replace all-thread threadfence
__device__ __forceinline__ void red_release(unsigned* p, unsigned v) {
    asm volatile("red.release.gpu.global.add.u32 [%0], %1;" :: "l"(p), "r"(v) : "memory");
}
__device__ __forceinline__ unsigned ld_acquire(const unsigned* p) {
    unsigned v;
    asm volatile("ld.acquire.gpu.global.u32 %0, [%1];" : "=r"(v) : "l"(p) : "memory");
    return v;
}

__device__ __forceinline__ uint32_t smem_u32(const void* p) {
    uint32_t a;
    asm("{ .reg .u64 t; cvta.to.shared.u64 t, %1; cvt.u32.u64 %0, t; }" : "=r"(a) : "l"(p));
    return a;
}

__device__ __forceinline__ void cp16(uint32_t s, const void* g) {
    asm volatile("cp.async.cg.shared.global [%0], [%1], 16;" :: "r"(s), "l"(g));
}

__device__ __forceinline__ void ldm_x4(uint32_t &r0, uint32_t &r1, uint32_t &r2,
                                       uint32_t &r3, uint32_t addr) {
    asm volatile("ldmatrix.sync.aligned.m8n8.x4.shared.b16 {%0,%1,%2,%3}, [%4];"
                 : "=r"(r0), "=r"(r1), "=r"(r2), "=r"(r3) : "r"(addr));
}

__device__ __forceinline__ void mma_f16(float* d, const uint32_t* a,
                                        const uint32_t* b) {
    asm volatile(
        "mma.sync.aligned.m16n8k16.row.col.f32.f16.f16.f32 "
        "{%0,%1,%2,%3}, {%4,%5,%6,%7}, {%8,%9}, {%0,%1,%2,%3};"
        : "+f"(d[0]), "+f"(d[1]), "+f"(d[2]), "+f"(d[3])
        : "r"(a[0]), "r"(a[1]), "r"(a[2]), "r"(a[3]), "r"(b[0]), "r"(b[1]));
}

// ---------------- small prep kernels ----------------
__global__ void reset_flags() {
    int i = threadIdx.x;
    if (i < 64) ((unsigned*)g_ctr2)[i] = 0u;
    if (i < LT) g_flag[i] = 0u;
}

__global__ void pack_w(const float* __restrict__ W, __half* __restrict__ Wp) {
    int i = blockIdx.x * 256 + threadIdx.x;
    if (i >= GG * FH) return;
    Wp[i] = __float2half(W[i]);
}

// Gate-interleaved W_hh permutation:
// smem/global row = nb*64 + wn*16 + gh*8 + fp*2 + gl
//   gate = gh*2 + gl ; feature(local) = wn*4 + fp
__global__ void pack_whh(const float* __restrict__ W) {
    size_t idx = (size_t)blockIdx.x * 256 + threadIdx.x;
    if (idx >= (size_t)GG * FH) return;
    int k   = (int)(idx % FH);
    int row = (int)(idx / FH);       // nb*64 + r
    int nb = row >> 6, r = row & 63;
    int wn = r >> 4, nl = r & 15;
    int gh = nl >> 3, rem = nl & 7;
    int fp = rem >> 1, gl = rem & 1;
    int gate = gh * 2 + gl;
    int fi = wn * 4 + fp;
    g_Whp[idx] = __float2half(W[(size_t)(gate * FH + nb * 16 + fi) * FH + k]);
}

// ---------------- GAT: one warp per graph (k-outer matmul) ----------------
__global__ __launch_bounds__(256) void gat_kernel(
    const float* __restrict__ src,
    const float* __restrict__ W_pre, const float* __restrict__ b_pre,
    const float* __restrict__ W_gat,
    const float* __restrict__ att_src, const float* __restrict__ att_dst,
    const float* __restrict__ b_gat,
    __half* __restrict__ Xp)
{
    __shared__ float Wg[32 * 32];
    __shared__ float xbuf[8][24][32];
    __shared__ float asd[8][24][2];

    int tid = threadIdx.x;
    for (int i = tid; i < 1024; i += 256) Wg[i] = W_gat[i];
    __syncthreads();

    int w = tid >> 5, h = tid & 31;
    int b = blockIdx.x * 8 + w;
    int n = b >> 8, l = b & 255;

    const float* s = src + (size_t)b * 72;
    float w0 = W_pre[h], w1 = W_pre[32 + h], w2 = W_pre[64 + h], bp = b_pre[h];

    #pragma unroll
    for (int j = 0; j < 24; j++) {
        float v = fmaf(s[j*3+2], w2, fmaf(s[j*3+1], w1, fmaf(s[j*3+0], w0, bp)));
        xbuf[w][j][h] = tanhf(v);
    }
    __syncwarp();

    float accj[24];
    #pragma unroll
    for (int j = 0; j < 24; j++) accj[j] = 0.f;
    #pragma unroll
    for (int k = 0; k < 32; k++) {
        float wv = Wg[k * 32 + h];
        #pragma unroll
        for (int j = 0; j < 24; j++)
            accj[j] = fmaf(xbuf[w][j][k], wv, accj[j]);
    }
    __syncwarp();

    float asrc = att_src[h], adst = att_dst[h];
    #pragma unroll
    for (int j = 0; j < 24; j++) {
        float ps = accj[j] * asrc, pd = accj[j] * adst;
        #pragma unroll
        for (int o = 16; o > 0; o >>= 1) {
            ps += __shfl_xor_sync(0xffffffffu, ps, o);
            pd += __shfl_xor_sync(0xffffffffu, pd, o);
        }
        if (h == 0) { asd[w][j][0] = ps; asd[w][j][1] = pd; }
        xbuf[w][j][h] = accj[j];
    }
    __syncwarp();

    float bg = b_gat[h];
    size_t rbase = (size_t)(l * 128 + n) * KH;
    #pragma unroll
    for (int j = 0; j < 24; j++) {
        int p = c_par[j];
        float g;
        if (p < 0) {
            g = xbuf[w][j][h];
        } else {
            float ad = asd[w][j][1];
            float es = ad + asd[w][j][0];
            float ep = ad + asd[w][p][0];
            es = es > 0.f ? es : 0.2f * es;
            ep = ep > 0.f ? ep : 0.2f * ep;
            float m  = fmaxf(es, ep);
            float ws = __expf(es - m), wp = __expf(ep - m);
            float inv = __fdividef(1.f, ws + wp);
            g = (ws * xbuf[w][j][h] + wp * xbuf[w][p][h]) * inv;
        }
        Xp[rbase + j * 32 + h] = __float2half(g + bg);
    }
}

// ---------------- mega kernel ----------------
__global__ __launch_bounds__(256, 1) void mega(
    const float* __restrict__ bih, const float* __restrict__ bhh,
    float* __restrict__ out)
{
    extern __shared__ __align__(16) char sm[];
    const uint32_t smb = smem_u32(sm);

    const int tid  = threadIdx.x;
    const int lane = tid & 31;
    const int warp = tid >> 5;

    if (blockIdx.x >= NRB) {
        // ================= producer role: 1-term fp16 GEMM =================
        const int gb = blockIdx.x - NRB;
        const __half* Ap = g_Xp;
        const __half* Bp = g_Wp;
        float* C = g_XW;

        const int wm = warp >> 2;
        const int wn = warp & 3;
        const int ldRow = tid >> 2;
        const int ldSeg = tid & 3;
        const uint32_t stRow = ldRow * ROWB + ldSeg * 16;
        const uint32_t aOff = (uint32_t)((wm * 64 + (lane & 7) + ((lane >> 3) & 1) * 8) * ROWB
                                         + ((lane >> 4) & 1) * 16);
        const uint32_t bOff = (uint32_t)(ATILE + (wn * 32 + (lane & 7) + ((lane >> 4) & 1) * 8) * ROWB
                                         + ((lane >> 3) & 1) * 16);

        for (int tile = gb; tile < NTILE; tile += NGB) {
            const int y = tile / 24;
            const int x = tile % 24;
            const int m0 = y * 128;
            const int n0 = x * 128;

            const __half* gA = Ap + (size_t)(m0 + ldRow) * KH + ldSeg * 8;
            const __half* gB = Bp + (size_t)(n0 + ldRow) * KH + ldSeg * 8;

            float acc[4][4][4];
            #pragma unroll
            for (int i = 0; i < 4; i++)
                #pragma unroll
                for (int j = 0; j < 4; j++)
                    #pragma unroll
                    for (int q = 0; q < 4; q++) acc[i][j][q] = 0.f;

            #pragma unroll
            for (int pc = 0; pc < GNST - 1; pc++) {
                uint32_t sb = smb + pc * STAGEB;
                int ko = pc * BK;
                #pragma unroll
                for (int i = 0; i < 2; i++) {
                    cp16(sb + stRow + i * 64 * ROWB,         gA + (size_t)i * 64 * KH + ko);
                    cp16(sb + ATILE + stRow + i * 64 * ROWB, gB + (size_t)i * 64 * KH + ko);
                }
                asm volatile("cp.async.commit_group;");
            }

            for (int kc = 0; kc < NKH; kc++) {
                asm volatile("cp.async.wait_group %0;" :: "n"(GNST - 2));
                __syncthreads();

                if (kc + GNST - 1 < NKH) {
                    uint32_t sb = smb + ((kc + GNST - 1) & (GNST - 1)) * STAGEB;
                    int ko = (kc + GNST - 1) * BK;
                    #pragma unroll
                    for (int i = 0; i < 2; i++) {
                        cp16(sb + stRow + i * 64 * ROWB,         gA + (size_t)i * 64 * KH + ko);
                        cp16(sb + ATILE + stRow + i * 64 * ROWB, gB + (size_t)i * 64 * KH + ko);
                    }
                }
                asm volatile("cp.async.commit_group;");

                const uint32_t soff = smb + (kc & (GNST - 1)) * STAGEB;
                #pragma unroll
                for (int ks = 0; ks < 2; ks++) {
                    uint32_t a[4][4], bq[4][2];
                    #pragma unroll
                    for (int tm = 0; tm < 4; tm++)
                        ldm_x4(a[tm][0], a[tm][1], a[tm][2], a[tm][3],
                               soff + aOff + tm * (16 * ROWB) + ks * 32);
                    #pragma unroll
                    for (int tb = 0; tb < 2; tb++) {
                        uint32_t r0, r1, r2, r3;
                        ldm_x4(r0, r1, r2, r3, soff + bOff + tb * (16 * ROWB) + ks * 32);
                        bq[2*tb][0] = r0; bq[2*tb][1] = r1;
                        bq[2*tb+1][0] = r2; bq[2*tb+1][1] = r3;
                    }
                    #pragma unroll
                    for (int tm = 0; tm < 4; tm++)
                        #pragma unroll
                        for (int tn = 0; tn < 4; tn++)
                            mma_f16(acc[tm][tn], a[tm], bq[tn]);
                }
            }
            asm volatile("cp.async.wait_group 0;");

            #pragma unroll
            for (int tm = 0; tm < 4; tm++) {
                int row = m0 + wm * 64 + tm * 16 + (lane >> 2);
                #pragma unroll
                for (int tn = 0; tn < 4; tn++) {
                    int col = n0 + wn * 32 + tn * 8 + (lane & 3) * 2;
                    float* p = C + (size_t)row * GG + col;
                    *(float2*)p                    = make_float2(acc[tm][tn][0], acc[tm][tn][1]);
                    *(float2*)(p + (size_t)8 * GG) = make_float2(acc[tm][tn][2], acc[tm][tn][3]);
                }
            }

            // release-publish: stores of all threads -> syncthreads -> tid0 release
            __syncthreads();
            if (tid == 0) red_release(&g_flag[y], 1u);
        }
        return;
    }

    // ====== consumer role: persistent LSTM (register-resident gate epilogue) ======
    const int b  = blockIdx.x;
    const int mb = b & 1;
    const int nb = b >> 1;
    const int m0 = mb * 64;

    const int wm = warp >> 2;        // 0..1: 32-row m strip
    const int wn = warp & 3;         // 0..3: 16-row n strip (4 features x 4 gates)

    const int fp   = lane & 3;
    const int feat = nb * 16 + wn * 4 + fp;
    const int mbase = m0 + wm * 32 + (lane >> 2);   // + tm*16 + rr*8

    // one-time resident W slice (12 chunks x 64 rows x 64 halfs)
    {
        const __half* Wb = g_Whp + (size_t)nb * 64 * FH;
        for (int i = tid; i < NWCH * 512; i += 256) {
            int chunk = i >> 9;
            int rem   = i & 511;
            int row   = rem >> 3, seg = rem & 7;
            cp16(smb + WBASE + chunk * WCHB + row * RROW + seg * 16,
                 Wb + (size_t)row * FH + chunk * RBK + seg * 8);
        }
        asm volatile("cp.async.commit_group;");
        asm volatile("cp.async.wait_group 0;");
    }

    float bias_r[4];
    #pragma unroll
    for (int g = 0; g < 4; g++) bias_r[g] = bih[g * FH + feat] + bhh[g * FH + feat];

    float creg[4] = {0.f, 0.f, 0.f, 0.f};   // cells: idx = tm*2 + rr

    __syncthreads();

    const uint32_t aOff = (uint32_t)((wm * 32 + (lane & 15)) * RROW
                                     + ((lane >> 4) & 1) * 16);
    const uint32_t bOffW = (uint32_t)((wn * 16 + (lane & 7) + ((lane >> 4) & 1) * 8) * RROW
                                      + ((lane >> 3) & 1) * 16);

    unsigned* ctr = &g_ctr2[mb][0];
    const float* xwbase = g_XW;

    for (int t = 0; t < LT; t++) {
        const __half* hin   = g_hp[(t + 1) & 1];
        __half*       houtp = g_hp[t & 1];
        const float*  xw    = xwbase + (size_t)t * NB * GG;

        // ---- combined acquire-waits: xw[t] ready + same-half h[t-1] published ----
        if (tid == 0) {
            while (ld_acquire(&g_flag[t]) < 24u) { __nanosleep(64); }
            if (t > 0) {
                unsigned target = 48u * (unsigned)t;
                while (ld_acquire(ctr) < target) { __nanosleep(32); }
            }
        }
        __syncthreads();

        // ---- issue h loads FIRST so xw LDG overlaps them ----
        if (t > 0) {
            #pragma unroll
            for (int j = 0; j < 12; j++) {
                int i = tid + j * 256;
                int chunk = i >> 9;
                int rem   = i & 511;
                int row   = rem >> 3, seg = rem & 7;
                cp16(smb + chunk * ACHB + row * RROW + seg * 16,
                     hin + (size_t)(m0 + row) * FH + chunk * RBK + seg * 8);
            }
            asm volatile("cp.async.commit_group;");
            #pragma unroll
            for (int j = 12; j < 24; j++) {
                int i = tid + j * 256;
                int chunk = i >> 9;
                int rem   = i & 511;
                int row   = rem >> 3, seg = rem & 7;
                cp16(smb + chunk * ACHB + row * RROW + seg * 16,
                     hin + (size_t)(m0 + row) * FH + chunk * RBK + seg * 8);
            }
            asm volatile("cp.async.commit_group;");
        }

        // xw prefetch for this thread's 4 cells (overlaps cp.async)
        float xwv[4][4];
        #pragma unroll
        for (int tm = 0; tm < 2; tm++)
            #pragma unroll
            for (int rr = 0; rr < 2; rr++) {
                int m = mbase + tm * 16 + rr * 8;
                const float* xwr = xw + (size_t)m * GG + feat;
                int idx = tm * 2 + rr;
                xwv[idx][0] = xwr[0];
                xwv[idx][1] = xwr[FH];
                xwv[idx][2] = xwr[2 * FH];
                xwv[idx][3] = xwr[3 * FH];
            }

        float acc[2][2][4];
        #pragma unroll
        for (int i = 0; i < 2; i++)
            #pragma unroll
            for (int j = 0; j < 2; j++)
                #pragma unroll
                for (int q = 0; q < 4; q++) acc[i][j][q] = 0.f;

        if (t > 0) {
            asm volatile("cp.async.wait_group 1;");
            __syncthreads();
            #pragma unroll
            for (int kc = 0; kc < 6; kc++) {
                const uint32_t soff = smb + kc * ACHB;
                const uint32_t woff = smb + WBASE + kc * WCHB;
                #pragma unroll
                for (int ks = 0; ks < RBK / 16; ks++) {
                    uint32_t a[2][4], bq[2][2];
                    #pragma unroll
                    for (int tm = 0; tm < 2; tm++)
                        ldm_x4(a[tm][0], a[tm][1], a[tm][2], a[tm][3],
                               soff + aOff + tm * (16 * RROW) + ks * 32);
                    {
                        uint32_t r0, r1, r2, r3;
                        ldm_x4(r0, r1, r2, r3, woff + bOffW + ks * 32);
                        bq[0][0] = r0; bq[0][1] = r1;
                        bq[1][0] = r2; bq[1][1] = r3;
                    }
                    #pragma unroll
                    for (int tm = 0; tm < 2; tm++)
                        #pragma unroll
                        for (int tn = 0; tn < 2; tn++)
                            mma_f16(acc[tm][tn], a[tm], bq[tn]);
                }
            }

            asm volatile("cp.async.wait_group 0;");
            __syncthreads();
            #pragma unroll
            for (int kc = 6; kc < 12; kc++) {
                const uint32_t soff = smb + kc * ACHB;
                const uint32_t woff = smb + WBASE + kc * WCHB;
                #pragma unroll
                for (int ks = 0; ks < RBK / 16; ks++) {
                    uint32_t a[2][4], bq[2][2];
                    #pragma unroll
                    for (int tm = 0; tm < 2; tm++)
                        ldm_x4(a[tm][0], a[tm][1], a[tm][2], a[tm][3],
                               soff + aOff + tm * (16 * RROW) + ks * 32);
                    {
                        uint32_t r0, r1, r2, r3;
                        ldm_x4(r0, r1, r2, r3, woff + bOffW + ks * 32);
                        bq[0][0] = r0; bq[0][1] = r1;
                        bq[1][0] = r2; bq[1][1] = r3;
                    }
                    #pragma unroll
                    for (int tm = 0; tm < 2; tm++)
                        #pragma unroll
                        for (int tn = 0; tn < 2; tn++)
                            mma_f16(acc[tm][tn], a[tm], bq[tn]);
                }
            }
        }

        // ---- register-resident epilogue: gates of cell (tm, rr) live in acc ----
        float hvv[4];
        #pragma unroll
        for (int tm = 0; tm < 2; tm++)
            #pragma unroll
            for (int rr = 0; rr < 2; rr++) {
                int idx = tm * 2 + rr;
                int m = mbase + tm * 16 + rr * 8;

                float gi = acc[tm][0][rr*2+0] + xwv[idx][0] + bias_r[0];
                float gf = acc[tm][0][rr*2+1] + xwv[idx][1] + bias_r[1];
                float gg = acc[tm][1][rr*2+0] + xwv[idx][2] + bias_r[2];
                float go = acc[tm][1][rr*2+1] + xwv[idx][3] + bias_r[3];

                float c  = fsigm(gf) * creg[idx] + fsigm(gi) * ftanh(gg);
                float hv = fsigm(go) * ftanh(c);
                creg[idx] = c;
                hvv[idx] = hv;

                houtp[(size_t)m * FH + feat] = __float2half(hv);
            }

        // release-publish h slice: stores -> syncthreads -> tid0 release
        __syncthreads();         // also: all ldmatrix reads of h[t-1] done
        if (tid == 0) red_release(ctr, 1u);

        // out stores overlap other blocks' arrivals
        #pragma unroll
        for (int tm = 0; tm < 2; tm++)
            #pragma unroll
            for (int rr = 0; rr < 2; rr++) {
                int idx = tm * 2 + rr;
                int m = mbase + tm * 16 + rr * 8;
                out[((size_t)m * LT + t) * FH + feat] = hvv[idx];
                if (t == LT - 1) {
                    out[(size_t)NB * LT * FH + (size_t)m * FH + feat]           = hvv[idx];
                    out[(size_t)NB * LT * FH + NB * FH + (size_t)m * FH + feat] = creg[idx];
                }
            }
    }
}

// ---------------- launch ----------------
extern "C" void kernel_launch(void* const* d_in, const int* in_sizes, int n_in,
                              void* d_out, int out_size)
{
    const float* src     = (const float*)d_in[0];
    const float* W_pre   = (const float*)d_in[1];
    const float* b_pre   = (const float*)d_in[2];
    const float* W_gat   = (const float*)d_in[3];
    const float* att_src = (const float*)d_in[4];
    const float* att_dst = (const float*)d_in[5];
    const float* b_gat   = (const float*)d_in[6];
    const float* W_ih    = (const float*)d_in[7];
    const float* W_hh    = (const float*)d_in[8];
    const float* b_ih    = (const float*)d_in[9];
    const float* b_hh    = (const float*)d_in[10];
    float* out = (float*)d_out;

    __half *Xp, *Wp;
    cudaGetSymbolAddress((void**)&Xp,  g_Xp);
    cudaGetSymbolAddress((void**)&Wp,  g_Wp);

    cudaFuncSetAttribute(mega, cudaFuncAttributeMaxDynamicSharedMemorySize,
                         MEGA_SMEM);

    // 0) prep
    reset_flags<<<1, 256>>>();
    pack_w<<<(GG * FH + 255) / 256, 256>>>(W_ih, Wp);
    pack_whh<<<(unsigned)(((size_t)GG * FH + 255) / 256), 256>>>(W_hh);

    // 1) GAT -> fp16 X
    gat_kernel<<<BG / 8, 256>>>(src, W_pre, b_pre, W_gat, att_src, att_dst, b_gat, Xp);

    // 2) fused producer-GEMM + persistent-LSTM
    mega<<<NRB + NGB, 256, MEGA_SMEM>>>(b_ih, b_hh, out);
}